// round 2
// baseline (speedup 1.0000x reference)
#include <cuda_runtime.h>
#include <cstdint>

// Problem constants (fixed by the reference)
#define N_USERS   100000
#define N_ITEMS   200000
#define N_NODES   (N_USERS + N_ITEMS)     // 300000
#define DIM       64
#define NE        (N_NODES * DIM)         // 19,200,000 floats
#define NE4       (NE / 4)                // 4,800,000 float4
#define USER_ELEM (N_USERS * DIM)         // 6,400,000

// Static scratch: two ping-pong embedding buffers (76.8 MB each)
__device__ float g_A[NE];
__device__ float g_B[NE];

// ---------------------------------------------------------------------------
// init: A = concat(user_emb, item_emb); out = same; B = 0
// ---------------------------------------------------------------------------
__global__ void k_init(const float4* __restrict__ user_emb,
                       const float4* __restrict__ item_emb,
                       float4* __restrict__ out,
                       float4* __restrict__ A,
                       float4* __restrict__ B) {
    int i = blockIdx.x * blockDim.x + threadIdx.x;
    if (i >= NE4) return;
    float4 v;
    if (i < USER_ELEM / 4) v = user_emb[i];
    else                   v = item_emb[i - USER_ELEM / 4];
    out[i] = v;
    A[i]   = v;
    B[i]   = make_float4(0.f, 0.f, 0.f, 0.f);
}

// ---------------------------------------------------------------------------
// accumulate layer result into out and zero the other ping-pong buffer
// out += src ; other = 0
// ---------------------------------------------------------------------------
__global__ void k_accum_zero(float4* __restrict__ out,
                             const float4* __restrict__ src,
                             float4* __restrict__ other) {
    int i = blockIdx.x * blockDim.x + threadIdx.x;
    if (i >= NE4) return;
    float4 o = out[i];
    float4 s = src[i];
    o.x += s.x; o.y += s.y; o.z += s.z; o.w += s.w;
    out[i]   = o;
    other[i] = make_float4(0.f, 0.f, 0.f, 0.f);
}

// ---------------------------------------------------------------------------
// final: out = (out + src) * 0.25
// ---------------------------------------------------------------------------
__global__ void k_final(float4* __restrict__ out,
                        const float4* __restrict__ src) {
    int i = blockIdx.x * blockDim.x + threadIdx.x;
    if (i >= NE4) return;
    float4 o = out[i];
    float4 s = src[i];
    o.x = (o.x + s.x) * 0.25f;
    o.y = (o.y + s.y) * 0.25f;
    o.z = (o.z + s.z) * 0.25f;
    o.w = (o.w + s.w) * 0.25f;
    out[i] = o;
}

// ---------------------------------------------------------------------------
// COO SpMM scatter: y[row] += val * x[col]   (16 lanes per edge, float4 each)
// ---------------------------------------------------------------------------
__global__ void k_scatter(const int* __restrict__ rows,
                          const int* __restrict__ cols,
                          const float* __restrict__ vals,
                          const float* __restrict__ x,
                          float* __restrict__ y,
                          int nnz) {
    int gid = blockIdx.x * blockDim.x + threadIdx.x;
    int e = gid >> 4;           // edge index (16 lanes per edge)
    if (e >= nnz) return;
    int j = (gid & 15) << 2;    // float offset within the 64-dim row

    int   r = rows[e];          // same-address broadcast across the 16 lanes
    int   c = cols[e];
    float v = vals[e];

    const float4 xv = *reinterpret_cast<const float4*>(x + (size_t)c * DIM + j);
    float mx = v * xv.x, my = v * xv.y, mz = v * xv.z, mw = v * xv.w;

    float* dst = y + (size_t)r * DIM + j;
    asm volatile("red.global.add.v4.f32 [%0], {%1, %2, %3, %4};"
                 :: "l"(dst), "f"(mx), "f"(my), "f"(mz), "f"(mw)
                 : "memory");
}

// ---------------------------------------------------------------------------
// launch
// ---------------------------------------------------------------------------
extern "C" void kernel_launch(void* const* d_in, const int* in_sizes, int n_in,
                              void* d_out, int out_size) {
    const float* user_emb = (const float*)d_in[0];
    const float* item_emb = (const float*)d_in[1];
    const int*   e_rows   = (const int*)d_in[2];
    const int*   e_cols   = (const int*)d_in[3];
    const float* e_vals   = (const float*)d_in[4];
    float* out = (float*)d_out;
    const int nnz = in_sizes[2];

    float* A;  cudaGetSymbolAddress((void**)&A, g_A);
    float* B;  cudaGetSymbolAddress((void**)&B, g_B);

    const int TB = 256;
    const int ew_blocks = (NE4 + TB - 1) / TB;
    const long long sc_threads = (long long)nnz * 16;
    const int sc_blocks = (int)((sc_threads + TB - 1) / TB);

    // out = A = concat(emb), B = 0
    k_init<<<ew_blocks, TB>>>((const float4*)user_emb, (const float4*)item_emb,
                              (float4*)out, (float4*)A, (float4*)B);

    // layer 1: B = S @ A
    k_scatter<<<sc_blocks, TB>>>(e_rows, e_cols, e_vals, A, B, nnz);
    // out += B ; A = 0
    k_accum_zero<<<ew_blocks, TB>>>((float4*)out, (const float4*)B, (float4*)A);

    // layer 2: A = S @ B
    k_scatter<<<sc_blocks, TB>>>(e_rows, e_cols, e_vals, B, A, nnz);
    // out += A ; B = 0
    k_accum_zero<<<ew_blocks, TB>>>((float4*)out, (const float4*)A, (float4*)B);

    // layer 3: B = S @ A
    k_scatter<<<sc_blocks, TB>>>(e_rows, e_cols, e_vals, A, B, nnz);
    // out = (out + B) / 4
    k_final<<<ew_blocks, TB>>>((float4*)out, (const float4*)B);
}

// round 3
// speedup vs baseline: 1.5090x; 1.5090x over previous
#include <cuda_runtime.h>
#include <cstdint>

// Problem constants (fixed by the reference)
#define N_USERS   100000
#define N_ITEMS   200000
#define N_NODES   (N_USERS + N_ITEMS)     // 300000
#define DIM       64
#define NE        (N_NODES * DIM)         // 19,200,000 floats
#define NE4       (NE / 4)                // 4,800,000 float4
#define USER4     (N_USERS * DIM / 4)     // 1,600,000 float4

// Static scratch: three layer-output buffers (76.8 MB each)
__device__ float g_B1[NE];
__device__ float g_B2[NE];
__device__ float g_B3[NE];

// ---------------------------------------------------------------------------
// zero all three layer buffers
// ---------------------------------------------------------------------------
__global__ void k_zero3(float4* __restrict__ b1,
                        float4* __restrict__ b2,
                        float4* __restrict__ b3) {
    int i = blockIdx.x * blockDim.x + threadIdx.x;
    if (i >= NE4) return;
    float4 z = make_float4(0.f, 0.f, 0.f, 0.f);
    b1[i] = z; b2[i] = z; b3[i] = z;
}

// ---------------------------------------------------------------------------
// final: out = 0.25 * (concat(user,item) + B1 + B2 + B3)
// ---------------------------------------------------------------------------
__global__ void k_final(float4* __restrict__ out,
                        const float4* __restrict__ user_emb,
                        const float4* __restrict__ item_emb,
                        const float4* __restrict__ b1,
                        const float4* __restrict__ b2,
                        const float4* __restrict__ b3) {
    int i = blockIdx.x * blockDim.x + threadIdx.x;
    if (i >= NE4) return;
    float4 e = (i < USER4) ? user_emb[i] : item_emb[i - USER4];
    float4 a = b1[i], b = b2[i], c = b3[i];
    float4 o;
    o.x = 0.25f * (e.x + a.x + b.x + c.x);
    o.y = 0.25f * (e.y + a.y + b.y + c.y);
    o.z = 0.25f * (e.z + a.z + b.z + c.z);
    o.w = 0.25f * (e.w + a.w + b.w + c.w);
    out[i] = o;
}

// ---------------------------------------------------------------------------
// red.global.add.v4.f32 helper
// ---------------------------------------------------------------------------
__device__ __forceinline__ void red_v4(float* dst, float4 m) {
    asm volatile("red.global.add.v4.f32 [%0], {%1, %2, %3, %4};"
                 :: "l"(dst), "f"(m.x), "f"(m.y), "f"(m.z), "f"(m.w)
                 : "memory");
}

// ---------------------------------------------------------------------------
// COO SpMM scatter, half-D pass: y[row, half:half+32] += val * x[col, half:half+32]
// 8 lanes per edge (one float4 each), 2 edges per thread for MLP.
// ---------------------------------------------------------------------------
__global__ void k_scatter_half(const int*   __restrict__ rows,
                               const int*   __restrict__ cols,
                               const float* __restrict__ vals,
                               const float* __restrict__ x,
                               float*       __restrict__ y,
                               int nnz, int halfOff) {
    int gid = blockIdx.x * blockDim.x + threadIdx.x;
    int grp = gid >> 3;                       // edge pair index
    int j   = ((gid & 7) << 2) + halfOff;     // float offset within row
    int e0 = grp * 2;
    if (e0 >= nnz) return;
    int e1 = e0 + 1;
    bool has1 = (e1 < nnz);

    int   r0 = __ldcs(rows + e0);
    int   c0 = __ldcs(cols + e0);
    float v0 = __ldcs(vals + e0);
    int r1 = 0, c1 = 0; float v1 = 0.f;
    if (has1) { r1 = __ldcs(rows + e1); c1 = __ldcs(cols + e1); v1 = __ldcs(vals + e1); }

    // issue both gathers before any red (MLP=2)
    float4 x0 = *reinterpret_cast<const float4*>(x + (size_t)c0 * DIM + j);
    float4 x1 = make_float4(0.f, 0.f, 0.f, 0.f);
    if (has1) x1 = *reinterpret_cast<const float4*>(x + (size_t)c1 * DIM + j);

    float4 m0 = make_float4(v0 * x0.x, v0 * x0.y, v0 * x0.z, v0 * x0.w);
    red_v4(y + (size_t)r0 * DIM + j, m0);
    if (has1) {
        float4 m1 = make_float4(v1 * x1.x, v1 * x1.y, v1 * x1.z, v1 * x1.w);
        red_v4(y + (size_t)r1 * DIM + j, m1);
    }
}

// ---------------------------------------------------------------------------
// Layer-1 variant: gathers directly from split user/item inputs (no concat copy)
// ---------------------------------------------------------------------------
__global__ void k_scatter_half_l1(const int*   __restrict__ rows,
                                  const int*   __restrict__ cols,
                                  const float* __restrict__ vals,
                                  const float* __restrict__ user_emb,
                                  const float* __restrict__ item_emb,
                                  float*       __restrict__ y,
                                  int nnz, int halfOff) {
    int gid = blockIdx.x * blockDim.x + threadIdx.x;
    int grp = gid >> 3;
    int j   = ((gid & 7) << 2) + halfOff;
    int e0 = grp * 2;
    if (e0 >= nnz) return;
    int e1 = e0 + 1;
    bool has1 = (e1 < nnz);

    int   r0 = __ldcs(rows + e0);
    int   c0 = __ldcs(cols + e0);
    float v0 = __ldcs(vals + e0);
    int r1 = 0, c1 = 0; float v1 = 0.f;
    if (has1) { r1 = __ldcs(rows + e1); c1 = __ldcs(cols + e1); v1 = __ldcs(vals + e1); }

    const float* s0 = (c0 < N_USERS) ? user_emb + (size_t)c0 * DIM
                                     : item_emb + (size_t)(c0 - N_USERS) * DIM;
    float4 x0 = *reinterpret_cast<const float4*>(s0 + j);
    float4 x1 = make_float4(0.f, 0.f, 0.f, 0.f);
    if (has1) {
        const float* s1 = (c1 < N_USERS) ? user_emb + (size_t)c1 * DIM
                                         : item_emb + (size_t)(c1 - N_USERS) * DIM;
        x1 = *reinterpret_cast<const float4*>(s1 + j);
    }

    float4 m0 = make_float4(v0 * x0.x, v0 * x0.y, v0 * x0.z, v0 * x0.w);
    red_v4(y + (size_t)r0 * DIM + j, m0);
    if (has1) {
        float4 m1 = make_float4(v1 * x1.x, v1 * x1.y, v1 * x1.z, v1 * x1.w);
        red_v4(y + (size_t)r1 * DIM + j, m1);
    }
}

// ---------------------------------------------------------------------------
// launch
// ---------------------------------------------------------------------------
extern "C" void kernel_launch(void* const* d_in, const int* in_sizes, int n_in,
                              void* d_out, int out_size) {
    const float* user_emb = (const float*)d_in[0];
    const float* item_emb = (const float*)d_in[1];
    const int*   e_rows   = (const int*)d_in[2];
    const int*   e_cols   = (const int*)d_in[3];
    const float* e_vals   = (const float*)d_in[4];
    float* out = (float*)d_out;
    const int nnz = in_sizes[2];

    float* B1; cudaGetSymbolAddress((void**)&B1, g_B1);
    float* B2; cudaGetSymbolAddress((void**)&B2, g_B2);
    float* B3; cudaGetSymbolAddress((void**)&B3, g_B3);

    const int TB = 256;
    const int ew_blocks = (NE4 + TB - 1) / TB;
    // threads per pass: ceil(nnz/2) groups * 8 lanes
    const long long sc_threads = ((long long)(nnz + 1) / 2) * 8;
    const int sc_blocks = (int)((sc_threads + TB - 1) / TB);

    // zero all layer buffers
    k_zero3<<<ew_blocks, TB>>>((float4*)B1, (float4*)B2, (float4*)B3);

    // layer 1: B1 = S @ emb  (two half-D passes, gather from split inputs)
    k_scatter_half_l1<<<sc_blocks, TB>>>(e_rows, e_cols, e_vals, user_emb, item_emb, B1, nnz, 0);
    k_scatter_half_l1<<<sc_blocks, TB>>>(e_rows, e_cols, e_vals, user_emb, item_emb, B1, nnz, 32);

    // layer 2: B2 = S @ B1
    k_scatter_half<<<sc_blocks, TB>>>(e_rows, e_cols, e_vals, B1, B2, nnz, 0);
    k_scatter_half<<<sc_blocks, TB>>>(e_rows, e_cols, e_vals, B1, B2, nnz, 32);

    // layer 3: B3 = S @ B2
    k_scatter_half<<<sc_blocks, TB>>>(e_rows, e_cols, e_vals, B2, B3, nnz, 0);
    k_scatter_half<<<sc_blocks, TB>>>(e_rows, e_cols, e_vals, B2, B3, nnz, 32);

    // out = 0.25 * (emb + B1 + B2 + B3)
    k_final<<<ew_blocks, TB>>>((float4*)out, (const float4*)user_emb, (const float4*)item_emb,
                               (const float4*)B1, (const float4*)B2, (const float4*)B3);
}